// round 8
// baseline (speedup 1.0000x reference)
#include <cuda_runtime.h>
#include <cuda_bf16.h>

#define NT 256
#define WPB 8                        // warps per block
#define GROUPS 9                     // column groups, 30 output cols each
#define STRIPS 8                     // 32-row strips (last is 30)
#define NTASK (GROUPS * STRIPS * 256)          // 18432 warp tasks
#define NBLK (NTASK / WPB)                     // 2304 blocks

__device__ float    g_part[NBLK];
__device__ unsigned g_cnt;   // zero-init; last block resets each call

// One sliding-window row step. All four flags are compile-time constants in
// the steady loop, hoisted runtime bools in the peeled iterations.
#define ROW_STEP(P, GSV, EMIT, PFV)                                          \
    do {                                                                      \
        float w20 = pf0, w21 = pf1, w22 = pf2;                                \
        pf0 = pf1 = pf2 = 0.0f;                                               \
        if ((PFV) && (!EDGE || qv)) {                                         \
            const float* pr_ = pb + ((P) + 3) * 256 + q;                      \
            pf0 = pr_[0]; pf1 = pr_[1]; pf2 = pr_[2];                         \
        }                                                                     \
        float sl;                                                             \
        sl = w00 * cE[0];                                                     \
        sl = fmaf(w01, cE[1], sl);                                            \
        sl = fmaf(w02, cE[2], sl);                                            \
        sl = fmaf(w10, cE[3], sl);                                            \
        sl = fmaf(w11, cE[4], sl);                                            \
        sl = fmaf(w12, cE[5], sl);                                            \
        sl = fmaf(w20, cE[6], sl);                                            \
        sl = fmaf(w21, cE[7], sl);                                            \
        sl = fmaf(w22, cE[8], sl);                                            \
        float gs = (GSV) ? sl : 0.0f;                                         \
        float up = __shfl_up_sync(0xFFFFFFFFu, gs, 1);                        \
        float dn = __shfl_down_sync(0xFFFFFFFFu, gs, 1);                      \
        float hs = up + fmaf(2.0f, gs, dn);                                   \
        if (EMIT) {                                                           \
            float sm = h0 + fmaf(2.0f, h1, hs);                               \
            if (outv) {                                                       \
                float d = sm - rb[((P) - 1) * 254 + q];                       \
                acc = fmaf(d, d, acc);                                        \
            }                                                                 \
        }                                                                     \
        h0 = h1; h1 = hs;                                                     \
        w00 = w10; w01 = w11; w02 = w12;                                      \
        w10 = w20; w11 = w21; w12 = w22;                                      \
    } while (0)

template <bool EDGE>
__device__ __forceinline__ float strip_loss(
    const float* __restrict__ pb, const float* __restrict__ rb,
    const float* __restrict__ RRrow,           // RR + bHW + 256
    const float* __restrict__ kLb, const float* __restrict__ kDb,
    float scale, int q, int lane, int Y0, int Y1)
{
    const bool qv   = EDGE ? (q >= 0 && q <= 253) : true;
    const bool outv = (EDGE ? qv : true) && (lane >= 1) && (lane <= 30);

    float rinv = qv ? (1.0f / RRrow[q + 1]) : 0.0f;

    // cE[uv] = scale * (kL[uv] + rinv * kD[uv]); scale has Gaussian 1/16 folded.
    float cE[9];
    #pragma unroll
    for (int i = 0; i < 9; i++)
        cE[i] = scale * fmaf(rinv, kDb[i], kLb[i]);

    // Window rows p..p+2 (3x3 per lane) + 1-row prefetch.
    float w00 = 0, w01 = 0, w02 = 0, w10 = 0, w11 = 0, w12 = 0;
    float pf0 = 0, pf1 = 0, pf2 = 0;
    if (!EDGE || qv) {
        if (Y0 >= 1) {
            const float* pr = pb + (Y0 - 1) * 256 + q;
            w00 = pr[0]; w01 = pr[1]; w02 = pr[2];
        }
        {
            const float* pr = pb + Y0 * 256 + q;
            w10 = pr[0]; w11 = pr[1]; w12 = pr[2];
        }
        {
            const float* pr = pb + (Y0 + 1) * 256 + q;   // row (Y0-1)+2
            pf0 = pr[0]; pf1 = pr[1]; pf2 = pr[2];
        }
    }

    float h0 = 0.0f, h1 = 0.0f, acc = 0.0f;

    // Prologue (2 iters, runtime top-boundary flag, no emission).
    const bool gs_top = (Y0 >= 1);
    ROW_STEP(Y0 - 1, gs_top, false, true);
    ROW_STEP(Y0,     true,   false, true);

    // Steady state: zero conditionals.
    #pragma unroll 4
    for (int p = Y0 + 1; p <= Y1 - 1; p++) {
        ROW_STEP(p, true, true, true);
    }

    // Epilogue (2 iters, hoisted bottom-boundary flags).
    const bool pfv_last = (Y1 + 3 <= 255);   // false only for the last strip
    const bool gs_bot   = (Y1 + 1 <= 253);   // false only for the last strip
    ROW_STEP(Y1,     true,   true, pfv_last);
    ROW_STEP(Y1 + 1, gs_bot, true, false);

    return acc;
}

__global__ __launch_bounds__(NT) void pde_loss_kernel(
    const float* __restrict__ pred,   // [256,256,256]
    const float* __restrict__ rhs,    // [256,254,254]
    const float* __restrict__ kL,     // [256,3,3]
    const float* __restrict__ kD,     // [256,3,3]
    const float* __restrict__ RR,     // [256,256,256] broadcast meshgrid
    const float* __restrict__ ZZ,     // [256,256,256]
    const float* __restrict__ G,      // [3,3] separable [1,2,1]^2/16
    float* __restrict__ out)
{
    const int tid  = threadIdx.x;
    const int lane = tid & 31;
    const int wid  = tid >> 5;

    const int task = blockIdx.x * WPB + wid;           // 0..NTASK-1
    const int b    = task / (GROUPS * STRIPS);
    const int rem  = task - b * (GROUPS * STRIPS);
    const int s    = rem / GROUPS;
    const int g    = rem - s * GROUPS;

    const int q  = 30 * g - 1 + lane;                  // GS column for this lane
    const int Y0 = s * 32;
    const int Y1 = (Y0 + 31 > 253) ? 253 : (Y0 + 31);

    const size_t bHW = (size_t)b * 65536;
    const float* pb = pred + bHW;
    const float* rb = rhs + (size_t)b * (254 * 254);
    const float* RRrow = RR + bHW + 256;

    float hr = RRrow[2] - RRrow[1];
    float hz = ZZ[bHW + 2 * 256 + 1] - ZZ[bHW + 256 + 1];
    float hr2 = hr * hr, hz2 = hz * hz;
    float scale = ((-2.0f * (hr2 + hz2)) / (hr2 * hz2)) * 0.0625f;

    float acc;
    if (g == 0 || g == GROUPS - 1)
        acc = strip_loss<true >(pb, rb, RRrow, kL + b * 9, kD + b * 9, scale, q, lane, Y0, Y1);
    else
        acc = strip_loss<false>(pb, rb, RRrow, kL + b * 9, kD + b * 9, scale, q, lane, Y0, Y1);

    // ---- block reduction, then last-block global reduction ----
    __shared__ float wpart[WPB];
    __shared__ unsigned is_last_s;

    #pragma unroll
    for (int off = 16; off > 0; off >>= 1)
        acc += __shfl_xor_sync(0xFFFFFFFFu, acc, off);
    if (lane == 0) wpart[wid] = acc;
    __syncthreads();

    if (tid == 0) {
        float ssum = 0.0f;
        #pragma unroll
        for (int w = 0; w < WPB; w++) ssum += wpart[w];
        __stcg(&g_part[blockIdx.x], ssum);
        __threadfence();
        unsigned old = atomicAdd(&g_cnt, 1u);
        is_last_s = (old == NBLK - 1) ? 1u : 0u;
    }
    __syncthreads();

    if (is_last_s) {
        double dsum = 0.0;
        const float4* p4 = (const float4*)g_part;
        for (int i = tid; i < NBLK / 4; i += NT) {
            float4 v = __ldcg(&p4[i]);
            dsum += (double)v.x + (double)v.y + (double)v.z + (double)v.w;
        }
        #pragma unroll
        for (int off = 16; off > 0; off >>= 1)
            dsum += __shfl_xor_sync(0xFFFFFFFFu, dsum, off);
        __shared__ double dpart[NT / 32];
        if (lane == 0) dpart[wid] = dsum;
        __syncthreads();
        if (tid == 0) {
            double t = 0.0;
            #pragma unroll
            for (int w = 0; w < NT / 32; w++) t += dpart[w];
            out[0] = (float)(t / (256.0 * 254.0 * 254.0));
            g_cnt = 0;  // reset for next graph replay
        }
    }
}

extern "C" void kernel_launch(void* const* d_in, const int* in_sizes, int n_in,
                              void* d_out, int out_size) {
    const float* pred = (const float*)d_in[0];
    const float* rhs  = (const float*)d_in[1];
    const float* kL   = (const float*)d_in[2];
    const float* kD   = (const float*)d_in[3];
    const float* RR   = (const float*)d_in[4];
    const float* ZZ   = (const float*)d_in[5];
    const float* G    = (const float*)d_in[6];
    float* out = (float*)d_out;

    pde_loss_kernel<<<NBLK, NT>>>(pred, rhs, kL, kD, RR, ZZ, G, out);
}

// round 9
// speedup vs baseline: 1.2785x; 1.2785x over previous
#include <cuda_runtime.h>
#include <cuda_bf16.h>

#define NT 256
#define WPB 8
#define GROUPS 5                      // 62 output cols per group
#define STRIPS 8                      // 32-row strips
#define NTASK (GROUPS * STRIPS * 256) // 10240 warp tasks
#define NBLK (NTASK / WPB)            // 1280 blocks

__device__ float    g_part[NBLK];
__device__ unsigned g_cnt;   // zero-init; last block resets each call

// Load pred row r, cols q0..q0+3, into dst[4] (two aligned float2; zeros if invalid).
#define LOADROW(R, dst)                                                      \
    do {                                                                     \
        int r_ = (R);                                                        \
        if (r_ >= 0 && r_ <= 255) {                                          \
            const float* base_ = pb + r_ * 256 + q0;                         \
            float2 e0_ = pl ? *(const float2*)(base_)     : make_float2(0.f, 0.f); \
            float2 e1_ = pl ? *(const float2*)(base_ + 2) : make_float2(0.f, 0.f); \
            dst[0] = e0_.x; dst[1] = e0_.y; dst[2] = e1_.x; dst[3] = e1_.y;  \
        } else {                                                             \
            dst[0] = dst[1] = dst[2] = dst[3] = 0.0f;                        \
        }                                                                    \
    } while (0)

__global__ __launch_bounds__(NT) void pde_loss_kernel(
    const float* __restrict__ pred,   // [256,256,256]
    const float* __restrict__ rhs,    // [256,254,254]
    const float* __restrict__ kL,     // [256,3,3]
    const float* __restrict__ kD,     // [256,3,3]
    const float* __restrict__ RR,     // [256,256,256] broadcast meshgrid
    const float* __restrict__ ZZ,     // [256,256,256]
    const float* __restrict__ G,      // [3,3] separable [1,2,1]^2/16
    float* __restrict__ out)
{
    const int tid  = threadIdx.x;
    const int lane = tid & 31;
    const int wid  = tid >> 5;

    const int task = blockIdx.x * WPB + wid;
    const int b    = task / (GROUPS * STRIPS);
    const int rem  = task - b * (GROUPS * STRIPS);
    const int s    = rem / STRIPS == 0 ? 0 : 0, sdummy = 0;  // (unused)
    const int st   = rem / GROUPS;
    const int g    = rem - st * GROUPS;

    const int q0 = 62 * g - 2 + 2 * lane;   // even -> aligned float2 loads
    const int q1 = q0 + 1;
    const int Y0 = st * 32;
    const int Y1 = (Y0 + 31 > 253) ? 253 : (Y0 + 31);

    const size_t bHW = (size_t)b * 65536;
    const float* pb = pred + bHW;
    const float* rb = rhs + (size_t)b * 64516;
    const float* RRrow = RR + bHW + 256;

    // Validity (per-lane, hoisted):
    const bool gv0 = (q0 >= 0) && (q0 <= 253);           // GS col q0 exists
    const bool gv1 = (q1 >= 0) && (q1 <= 253);           // GS col q1 exists
    const bool ev0 = (lane >= 1) && (q0 <= 253);         // emit x=q0
    const bool ev1 = (lane <= 30) && (q1 >= 0) && (q1 <= 253);  // emit x=q1
    const bool pl  = (q0 >= 0) && (q0 <= 252);           // pred cols q0..q0+3 valid

    float hr = RRrow[2] - RRrow[1];
    float hz = ZZ[bHW + 2 * 256 + 1] - ZZ[bHW + 256 + 1];
    float hr2 = hr * hr, hz2 = hz * hz;
    float scale = ((-2.0f * (hr2 + hz2)) / (hr2 * hz2)) * 0.0625f;

    float rinv0 = gv0 ? (1.0f / RRrow[q0 + 1]) : 0.0f;
    float rinv1 = gv1 ? (1.0f / RRrow[q1 + 1]) : 0.0f;

    // Per-column folded stencils: cE[uv] = scale * (kL + rinv*kD).
    float cE0[9], cE1[9];
    #pragma unroll
    for (int i = 0; i < 9; i++) {
        float l = kL[b * 9 + i], d = kD[b * 9 + i];
        cE0[i] = scale * fmaf(rinv0, d, l);
        cE1[i] = scale * fmaf(rinv1, d, l);
    }

    // Sliding window: rows p, p+1, p+2 (4 cols each) + 1-row prefetch.
    float w0[4], w1[4], w2[4], pf[4];
    LOADROW(Y0 - 1, w0);
    LOADROW(Y0,     w1);
    LOADROW(Y0 + 1, w2);
    LOADROW(Y0 + 2, pf);

    float rpf0 = 0.0f, rpf1 = 0.0f;   // rhs prefetch (row oy=p, consumed next iter)
    float h00 = 0.0f, h01 = 0.0f, h10 = 0.0f, h11 = 0.0f;
    float acc = 0.0f;

    #pragma unroll 5
    for (int p = Y0 - 1; p <= Y1 + 1; ++p) {
        // Consume rhs prefetched last iteration (row p-1).
        float rc0 = rpf0, rc1 = rpf1;
        // Prefetch rhs row p (emitted next iteration as oy=p).
        if (p >= Y0 && p <= Y1) {
            rpf0 = ev0 ? __ldg(rb + p * 254 + q0) : 0.0f;
            rpf1 = ev1 ? __ldg(rb + p * 254 + q1) : 0.0f;
        }

        // GS row p for both columns (window rows p..p+2 = w0,w1,w2).
        float s0, s1;
        s0 = w0[0] * cE0[0];              s1 = w0[1] * cE1[0];
        s0 = fmaf(w0[1], cE0[1], s0);     s1 = fmaf(w0[2], cE1[1], s1);
        s0 = fmaf(w0[2], cE0[2], s0);     s1 = fmaf(w0[3], cE1[2], s1);
        s0 = fmaf(w1[0], cE0[3], s0);     s1 = fmaf(w1[1], cE1[3], s1);
        s0 = fmaf(w1[1], cE0[4], s0);     s1 = fmaf(w1[2], cE1[4], s1);
        s0 = fmaf(w1[2], cE0[5], s0);     s1 = fmaf(w1[3], cE1[5], s1);
        s0 = fmaf(w2[0], cE0[6], s0);     s1 = fmaf(w2[1], cE1[6], s1);
        s0 = fmaf(w2[1], cE0[7], s0);     s1 = fmaf(w2[2], cE1[7], s1);
        s0 = fmaf(w2[2], cE0[8], s0);     s1 = fmaf(w2[3], cE1[8], s1);

        bool prow = (p >= 0 && p <= 253);
        float gs0 = (prow && gv0) ? s0 : 0.0f;
        float gs1 = (prow && gv1) ? s1 : 0.0f;

        // Horizontal [1,2,1]: neighbors via shuffle.
        float gl = __shfl_up_sync(0xFFFFFFFFu, gs1, 1);    // GS[q0-1]
        float gr = __shfl_down_sync(0xFFFFFFFFu, gs0, 1);  // GS[q1+1]
        float hs0 = gl  + fmaf(2.0f, gs0, gs1);
        float hs1 = gs0 + fmaf(2.0f, gs1, gr);

        // Vertical [1,2,1] + MSE for oy = p-1.
        if (p >= Y0 + 1) {
            float sm0 = h00 + fmaf(2.0f, h10, hs0);
            float sm1 = h01 + fmaf(2.0f, h11, hs1);
            float d0 = ev0 ? (sm0 - rc0) : 0.0f;
            float d1 = ev1 ? (sm1 - rc1) : 0.0f;
            acc = fmaf(d0, d0, acc);
            acc = fmaf(d1, d1, acc);
        }

        h00 = h10; h01 = h11; h10 = hs0; h11 = hs1;
        w0[0]=w1[0]; w0[1]=w1[1]; w0[2]=w1[2]; w0[3]=w1[3];
        w1[0]=w2[0]; w1[1]=w2[1]; w1[2]=w2[2]; w1[3]=w2[3];
        w2[0]=pf[0]; w2[1]=pf[1]; w2[2]=pf[2]; w2[3]=pf[3];
        LOADROW(p + 4, pf);
    }

    // ---- block reduction, then last-block global reduction ----
    __shared__ float wpart[WPB];
    __shared__ unsigned is_last_s;

    #pragma unroll
    for (int off = 16; off > 0; off >>= 1)
        acc += __shfl_xor_sync(0xFFFFFFFFu, acc, off);
    if (lane == 0) wpart[wid] = acc;
    __syncthreads();

    if (tid == 0) {
        float ssum = 0.0f;
        #pragma unroll
        for (int w = 0; w < WPB; w++) ssum += wpart[w];
        __stcg(&g_part[blockIdx.x], ssum);
        __threadfence();
        unsigned old = atomicAdd(&g_cnt, 1u);
        is_last_s = (old == NBLK - 1) ? 1u : 0u;
    }
    __syncthreads();

    if (is_last_s) {
        double dsum = 0.0;
        const float4* p4 = (const float4*)g_part;
        for (int i = tid; i < NBLK / 4; i += NT) {
            float4 v = __ldcg(&p4[i]);
            dsum += (double)v.x + (double)v.y + (double)v.z + (double)v.w;
        }
        #pragma unroll
        for (int off = 16; off > 0; off >>= 1)
            dsum += __shfl_xor_sync(0xFFFFFFFFu, dsum, off);
        __shared__ double dpart[NT / 32];
        if (lane == 0) dpart[wid] = dsum;
        __syncthreads();
        if (tid == 0) {
            double t = 0.0;
            #pragma unroll
            for (int w = 0; w < NT / 32; w++) t += dpart[w];
            out[0] = (float)(t / (256.0 * 254.0 * 254.0));
            g_cnt = 0;  // reset for next graph replay
        }
    }
}

extern "C" void kernel_launch(void* const* d_in, const int* in_sizes, int n_in,
                              void* d_out, int out_size) {
    const float* pred = (const float*)d_in[0];
    const float* rhs  = (const float*)d_in[1];
    const float* kL   = (const float*)d_in[2];
    const float* kD   = (const float*)d_in[3];
    const float* RR   = (const float*)d_in[4];
    const float* ZZ   = (const float*)d_in[5];
    const float* G    = (const float*)d_in[6];
    float* out = (float*)d_out;

    pde_loss_kernel<<<NBLK, NT>>>(pred, rhs, kL, kD, RR, ZZ, G, out);
}

// round 12
// speedup vs baseline: 1.5751x; 1.2320x over previous
#include <cuda_runtime.h>
#include <cuda_bf16.h>

#define NT 128
#define WPB 4
#define GROUPS 5                       // 62 output cols per group (mapping verified)
#define STRIPS 8                       // 32-row strips
#define NTASK (GROUPS * STRIPS * 256)  // 10240 warp tasks
#define NBLK (NTASK / WPB)             // 2560 blocks

__device__ float    g_part[NBLK];
__device__ unsigned g_cnt;   // zero-init; last block resets each call

// Unconditional 4-col row load from clamped, always-in-bounds addresses.
#define LOADROW(R, dst)                                            \
    do {                                                           \
        const float* a_ = pq + (R) * 256;                          \
        float2 e0_ = *(const float2*)(a_);                         \
        float2 e1_ = *(const float2*)(a_ + 2);                     \
        dst[0] = e0_.x; dst[1] = e0_.y; dst[2] = e1_.x; dst[3] = e1_.y; \
    } while (0)

__global__ __launch_bounds__(NT) void pde_loss_kernel(
    const float* __restrict__ pred,   // [256,256,256]
    const float* __restrict__ rhs,    // [256,254,254]
    const float* __restrict__ kL,     // [256,3,3]
    const float* __restrict__ kD,     // [256,3,3]
    const float* __restrict__ RR,     // [256,256,256] broadcast meshgrid
    const float* __restrict__ ZZ,     // [256,256,256]
    const float* __restrict__ G,      // [3,3] separable [1,2,1]^2/16
    float* __restrict__ out)
{
    const int tid  = threadIdx.x;
    const int lane = tid & 31;
    const int wid  = tid >> 5;

    const int task = blockIdx.x * WPB + wid;
    const int b    = task / (GROUPS * STRIPS);
    const int rem  = task - b * (GROUPS * STRIPS);
    const int st   = rem / GROUPS;
    const int g    = rem - st * GROUPS;

    const int q0 = 62 * g - 2 + 2 * lane;   // even
    const int q1 = q0 + 1;
    const int Y0 = st * 32;
    const int Y1 = (Y0 + 31 > 253) ? 253 : (Y0 + 31);

    const size_t bHW = (size_t)b * 65536;
    const float* pb = pred + bHW;
    const float* rb = rhs + (size_t)b * 64516;
    const float* RRrow = RR + bHW + 256;

    // Validity masks (hoisted; garbage loads from clamped addresses are masked here).
    const bool  gv0 = (q0 >= 0) && (q0 <= 253);
    const bool  gv1 = (q1 >= 0) && (q1 <= 253);
    const float m0  = ((lane >= 1) && (q0 <= 253)) ? 1.0f : 0.0f;
    const float m1  = ((lane <= 30) && (q1 >= 0) && (q1 <= 253)) ? 1.0f : 0.0f;

    // Clamped column bases (always in-bounds).
    const int qc  = min(max(q0, 0), 252);        // pred float2 base, stays even
    const int rq0 = min(max(q0, 0), 253);
    const int rq1 = min(max(q1, 0), 253);
    const float* pq = pb + qc;
    const float* rq = rb + rq0;
    const int    rd = rq1 - rq0;

    float hr = RRrow[2] - RRrow[1];
    float hz = ZZ[bHW + 2 * 256 + 1] - ZZ[bHW + 256 + 1];
    float hr2 = hr * hr, hz2 = hz * hz;
    float scale = ((-2.0f * (hr2 + hz2)) / (hr2 * hz2)) * 0.0625f;

    // RRrow[q+1] is in-bounds for all q in [-2, 309]; masked lanes never use it.
    float rinv0 = 1.0f / RRrow[q0 + 1];
    float rinv1 = 1.0f / RRrow[q1 + 1];
    if (!gv0) rinv0 = 0.0f;
    if (!gv1) rinv1 = 0.0f;

    // Folded per-column stencils: cE[uv] = scale * (kL + rinv*kD).
    float cE0[9], cE1[9];
    #pragma unroll
    for (int i = 0; i < 9; i++) {
        float l = kL[b * 9 + i], d = kD[b * 9 + i];
        cE0[i] = scale * fmaf(rinv0, d, l);
        cE1[i] = scale * fmaf(rinv1, d, l);
    }

    // Sliding window rows p..p+2 (4 cols) + 1-row prefetch; clamped rows.
    float w0[4], w1[4], w2[4], pf[4];
    LOADROW(max(Y0 - 1, 0), w0);
    LOADROW(Y0,             w1);
    LOADROW(Y0 + 1,         w2);
    LOADROW(Y0 + 2,         pf);

    float rpf0 = 0.0f, rpf1 = 0.0f;
    float h00 = 0.0f, h01 = 0.0f, h10 = 0.0f, h11 = 0.0f;
    float acc = 0.0f;

    #pragma unroll 4
    for (int p = Y0 - 1; p <= Y1 + 1; ++p) {
        // Consume rhs prefetched last iteration (row p-1); prefetch row p (clamped).
        float rc0 = rpf0, rc1 = rpf1;
        {
            int rrow = min(max(p, 0), 253);
            const float* ra = rq + rrow * 254;
            rpf0 = __ldg(ra);
            rpf1 = __ldg(ra + rd);
        }

        // GS row p for both columns.
        float s0, s1;
        s0 = w0[0] * cE0[0];              s1 = w0[1] * cE1[0];
        s0 = fmaf(w0[1], cE0[1], s0);     s1 = fmaf(w0[2], cE1[1], s1);
        s0 = fmaf(w0[2], cE0[2], s0);     s1 = fmaf(w0[3], cE1[2], s1);
        s0 = fmaf(w1[0], cE0[3], s0);     s1 = fmaf(w1[1], cE1[3], s1);
        s0 = fmaf(w1[1], cE0[4], s0);     s1 = fmaf(w1[2], cE1[4], s1);
        s0 = fmaf(w1[2], cE0[5], s0);     s1 = fmaf(w1[3], cE1[5], s1);
        s0 = fmaf(w2[0], cE0[6], s0);     s1 = fmaf(w2[1], cE1[6], s1);
        s0 = fmaf(w2[1], cE0[7], s0);     s1 = fmaf(w2[2], cE1[7], s1);
        s0 = fmaf(w2[2], cE0[8], s0);     s1 = fmaf(w2[3], cE1[8], s1);

        const bool pv = ((unsigned)p <= 253u);
        float gs0 = (pv && gv0) ? s0 : 0.0f;
        float gs1 = (pv && gv1) ? s1 : 0.0f;

        // Horizontal [1,2,1] via shuffles.
        float gl = __shfl_up_sync(0xFFFFFFFFu, gs1, 1);    // GS[q0-1]
        float gr = __shfl_down_sync(0xFFFFFFFFu, gs0, 1);  // GS[q1+1]
        float hs0 = gl  + fmaf(2.0f, gs0, gs1);
        float hs1 = gs0 + fmaf(2.0f, gs1, gr);

        // Vertical [1,2,1] + MSE for oy = p-1 (masks absorb garbage rc on edge lanes).
        if (p >= Y0 + 1) {
            float sm0 = h00 + fmaf(2.0f, h10, hs0);
            float sm1 = h01 + fmaf(2.0f, h11, hs1);
            float d0 = (sm0 - rc0) * m0;
            float d1 = (sm1 - rc1) * m1;
            acc = fmaf(d0, d0, acc);
            acc = fmaf(d1, d1, acc);
        }

        h00 = h10; h01 = h11; h10 = hs0; h11 = hs1;
        w0[0]=w1[0]; w0[1]=w1[1]; w0[2]=w1[2]; w0[3]=w1[3];
        w1[0]=w2[0]; w1[1]=w2[1]; w1[2]=w2[2]; w1[3]=w2[3];
        w2[0]=pf[0]; w2[1]=pf[1]; w2[2]=pf[2]; w2[3]=pf[3];
        LOADROW(min(p + 4, 255), pf);
    }

    // ---- block reduction, then last-block global reduction ----
    __shared__ float wpart[WPB];
    __shared__ unsigned is_last_s;

    #pragma unroll
    for (int off = 16; off > 0; off >>= 1)
        acc += __shfl_xor_sync(0xFFFFFFFFu, acc, off);
    if (lane == 0) wpart[wid] = acc;
    __syncthreads();

    if (tid == 0) {
        float ssum = 0.0f;
        #pragma unroll
        for (int w = 0; w < WPB; w++) ssum += wpart[w];
        __stcg(&g_part[blockIdx.x], ssum);
        __threadfence();
        unsigned old = atomicAdd(&g_cnt, 1u);
        is_last_s = (old == NBLK - 1) ? 1u : 0u;
    }
    __syncthreads();

    if (is_last_s) {
        double dsum = 0.0;
        const float4* p4 = (const float4*)g_part;
        for (int i = tid; i < NBLK / 4; i += NT) {
            float4 v = __ldcg(&p4[i]);
            dsum += (double)v.x + (double)v.y + (double)v.z + (double)v.w;
        }
        #pragma unroll
        for (int off = 16; off > 0; off >>= 1)
            dsum += __shfl_xor_sync(0xFFFFFFFFu, dsum, off);
        __shared__ double dpart[NT / 32];
        if (lane == 0) dpart[wid] = dsum;
        __syncthreads();
        if (tid == 0) {
            double t = 0.0;
            #pragma unroll
            for (int w = 0; w < NT / 32; w++) t += dpart[w];
            out[0] = (float)(t / (256.0 * 254.0 * 254.0));
            g_cnt = 0;  // reset for next graph replay
        }
    }
}

extern "C" void kernel_launch(void* const* d_in, const int* in_sizes, int n_in,
                              void* d_out, int out_size) {
    const float* pred = (const float*)d_in[0];
    const float* rhs  = (const float*)d_in[1];
    const float* kL   = (const float*)d_in[2];
    const float* kD   = (const float*)d_in[3];
    const float* RR   = (const float*)d_in[4];
    const float* ZZ   = (const float*)d_in[5];
    const float* G    = (const float*)d_in[6];
    float* out = (float*)d_out;

    pde_loss_kernel<<<NBLK, NT>>>(pred, rhs, kL, kD, RR, ZZ, G, out);
}